// round 3
// baseline (speedup 1.0000x reference)
#include <cuda_runtime.h>
#include <cuda_bf16.h>
#include <math.h>

// Problem constants
#define B   64
#define H   512
#define W   512
#define C   3
#define HW  (H * W)
#define NPIX_PER_IMG (HW * C)       // 786432 floats per image
#define NUM_LAYERS 2

// magnitude constants (MAG = 0.5)
#define ENH_F     1.45f
#define INV_ENH_F (1.0f / 1.45f)
#define FILL_V    0.5f
#define ROT_RAD   0.26179938779914943653855361527329f  // 15 deg in radians
#define SHEAR_AMT 0.15f
#define TRANS_AMT 76.8f   // 0.15 * 512
#define CENTER    255.5f  // (512-1)*0.5

// Scratch for the ping-pong between layer 0 and layer 1 (allocation-free rule:
// __device__ global array).
__device__ float g_scratch[(size_t)B * NPIX_PER_IMG];
// Per-image sum accumulators for the contrast branch.
__device__ double g_sums[B];

// ---------------------------------------------------------------------------
__global__ void zero_sums_kernel() {
    int t = threadIdx.x;
    if (t < B) g_sums[t] = 0.0;
}

// Per-image mean (only when this layer's op is contrast, op id 6).
// grid: (blocks_per_img, B), block: 256
__global__ __launch_bounds__(256) void mean_kernel(
    const float* __restrict__ src,
    const int* __restrict__ op_ids,
    int layer)
{
    int b = blockIdx.y;
    if (op_ids[b * NUM_LAYERS + layer] != 6) return;

    const float* img = src + (size_t)b * NPIX_PER_IMG;
    double acc = 0.0;
    int stride = gridDim.x * blockDim.x;
    for (int i = blockIdx.x * blockDim.x + threadIdx.x; i < NPIX_PER_IMG; i += stride)
        acc += (double)img[i];

    __shared__ double red[256];
    red[threadIdx.x] = acc;
    __syncthreads();
    for (int s = 128; s > 0; s >>= 1) {
        if (threadIdx.x < s) red[threadIdx.x] += red[threadIdx.x + s];
        __syncthreads();
    }
    if (threadIdx.x == 0) atomicAdd(&g_sums[b], red[0]);
}

// ---------------------------------------------------------------------------
// Bilinear sample with out-of-bounds fill, matching the JAX reference exactly:
// validity is tested on the un-clipped corner coordinate, indices are clipped.
__device__ __forceinline__ void bilinear_sample(
    const float* __restrict__ img, float xi, float yi, float out[3])
{
    float x0 = floorf(xi), y0 = floorf(yi);
    float wx = xi - x0,    wy = yi - y0;

    float wgt[4] = { (1.f - wx) * (1.f - wy),
                     wx         * (1.f - wy),
                     (1.f - wx) * wy,
                     wx         * wy };

    out[0] = 0.f; out[1] = 0.f; out[2] = 0.f;

#pragma unroll
    for (int k = 0; k < 4; ++k) {
        float xx = x0 + (float)(k & 1);
        float yy = y0 + (float)(k >> 1);
        bool valid = (xx >= 0.f) && (xx <= (float)(W - 1)) &&
                     (yy >= 0.f) && (yy <= (float)(H - 1));
        int xc = (int)fminf(fmaxf(xx, 0.f), (float)(W - 1));
        int yc = (int)fminf(fmaxf(yy, 0.f), (float)(H - 1));
        const float* p = img + ((size_t)yc * W + xc) * C;
        float w = wgt[k];
#pragma unroll
        for (int c = 0; c < C; ++c) {
            float v = valid ? p[c] : FILL_V;
            out[c] += w * v;
        }
    }
}

__device__ __forceinline__ float clip01(float v) {
    return fminf(fmaxf(v, 0.f), 1.f);
}

// ---------------------------------------------------------------------------
// Main distort kernel: one thread per pixel (3 channels).
// grid: (HW/256, B), block: 256. Every block is branch-uniform (op depends
// only on the image index).
__global__ __launch_bounds__(256) void distort_kernel(
    const float* __restrict__ src,
    float* __restrict__ dst,
    const int* __restrict__ op_ids,
    const int* __restrict__ signs,
    int layer)
{
    int b   = blockIdx.y;
    int pix = blockIdx.x * blockDim.x + threadIdx.x;   // 0 .. HW-1
    int x   = pix & (W - 1);
    int y   = pix >> 9;                                 // W == 512

    const float* img = src + (size_t)b * NPIX_PER_IMG;
    float* out       = dst + (size_t)b * NPIX_PER_IMG + (size_t)pix * C;

    int   op = op_ids[b * NUM_LAYERS + layer];
    float s  = 2.0f * (float)signs[b * NUM_LAYERS + layer] - 1.0f;

    float xs = (float)x, ys = (float)y;
    float dx = xs - CENTER, dy = ys - CENTER;

    if (op <= 4) {
        // Affine branches: compute inverse-map coordinates, bilinear resample.
        float xi, yi;
        if (op == 0) {          // rotate
            float th = s * ROT_RAD;
            float co = cosf(th), si = sinf(th);
            xi = co * dx + si * dy + CENTER;
            yi = -si * dx + co * dy + CENTER;
        } else if (op == 1) {   // shear_x
            float sh = s * SHEAR_AMT;
            xi = dx - sh * dy + CENTER;
            yi = ys;
        } else if (op == 2) {   // shear_y
            float sh = s * SHEAR_AMT;
            xi = xs;
            yi = -sh * dx + dy + CENTER;
        } else if (op == 3) {   // trans_x
            xi = xs - s * TRANS_AMT;
            yi = ys;
        } else {                // trans_y
            xi = xs;
            yi = ys - s * TRANS_AMT;
        }
        float v[3];
        bilinear_sample(img, xi, yi, v);
        out[0] = v[0]; out[1] = v[1]; out[2] = v[2];
    } else if (op == 5) {
        // brightness: clip(f * img)
        float f = (s > 0.f) ? ENH_F : INV_ENH_F;
        const float* p = img + (size_t)pix * C;
#pragma unroll
        for (int c = 0; c < C; ++c)
            out[c] = clip01(f * p[c]);
    } else if (op == 6) {
        // contrast: clip(mean + f*(img - mean))
        float f = (s > 0.f) ? ENH_F : INV_ENH_F;
        float m = (float)(g_sums[b] * (1.0 / (double)NPIX_PER_IMG));
        const float* p = img + (size_t)pix * C;
#pragma unroll
        for (int c = 0; c < C; ++c)
            out[c] = clip01(m + f * (p[c] - m));
    } else {
        // sharpness: clip(smooth + f*(img - smooth)); 3x3 PIL smooth kernel,
        // edge-clamped padding.
        float f = (s > 0.f) ? ENH_F : INV_ENH_F;
        float sm[3] = {0.f, 0.f, 0.f};
        const float inv13 = 1.0f / 13.0f;
#pragma unroll
        for (int i = 0; i < 3; ++i) {
#pragma unroll
            for (int j = 0; j < 3; ++j) {
                int yy = y + i - 1;
                int xx = x + j - 1;
                yy = min(max(yy, 0), H - 1);
                xx = min(max(xx, 0), W - 1);
                float kw = ((i == 1 && j == 1) ? 5.0f : 1.0f) * inv13;
                const float* p = img + ((size_t)yy * W + xx) * C;
#pragma unroll
                for (int c = 0; c < C; ++c)
                    sm[c] += kw * p[c];
            }
        }
        const float* p = img + (size_t)pix * C;
#pragma unroll
        for (int c = 0; c < C; ++c)
            out[c] = clip01(sm[c] + f * (p[c] - sm[c]));
    }
}

// ---------------------------------------------------------------------------
extern "C" void kernel_launch(void* const* d_in, const int* in_sizes, int n_in,
                              void* d_out, int out_size)
{
    const float* images = (const float*)d_in[0];
    const int*   op_ids = (const int*)d_in[1];
    const int*   signs  = (const int*)d_in[2];
    float* out = (float*)d_out;

    float* scratch;
    cudaGetSymbolAddress((void**)&scratch, g_scratch);

    dim3 dgrid(HW / 256, B);
    dim3 mgrid(48, B);

    // Layer 0: images -> scratch
    zero_sums_kernel<<<1, 64>>>();
    mean_kernel<<<mgrid, 256>>>(images, op_ids, 0);
    distort_kernel<<<dgrid, 256>>>(images, scratch, op_ids, signs, 0);

    // Layer 1: scratch -> out
    zero_sums_kernel<<<1, 64>>>();
    mean_kernel<<<mgrid, 256>>>(scratch, op_ids, 1);
    distort_kernel<<<dgrid, 256>>>(scratch, out, op_ids, signs, 1);
}

// round 5
// speedup vs baseline: 1.1618x; 1.1618x over previous
#include <cuda_runtime.h>
#include <cuda_bf16.h>
#include <math.h>

// Problem constants
#define B   64
#define H   512
#define W   512
#define C   3
#define HW  (H * W)
#define NPIX_PER_IMG (HW * C)       // 786432 floats per image
#define NUM_LAYERS 2
#define NQUAD (HW / 4)              // 65536 quads (4 consecutive x-pixels) per image

// magnitude constants (MAG = 0.5)
#define ENH_F     1.45f
#define INV_ENH_F (1.0f / 1.45f)
#define FILL_V    0.5f
#define ROT_RAD   0.26179938779914943653855361527329f  // 15 deg in radians
#define SHEAR_AMT 0.15f
#define TRANS_AMT 76.8f   // 0.15 * 512
#define CENTER    255.5f  // (512-1)*0.5

// Ping-pong scratch (allocation-free rule: __device__ global array).
__device__ float g_scratch[(size_t)B * NPIX_PER_IMG];
// Per-image sums: [0][b] = layer-0 contrast mean source (over input images),
//                 [1][b] = layer-1 contrast mean source (over layer-0 output).
__device__ double g_sums2[2][B];

// ---------------------------------------------------------------------------
// Per-image mean over the ORIGINAL images, only when layer-0 op is contrast.
__global__ __launch_bounds__(256) void mean_kernel(
    const float* __restrict__ src,
    const int* __restrict__ op_ids)
{
    int b = blockIdx.y;
    if (op_ids[b * NUM_LAYERS + 0] != 6) return;

    const float4* img4 = (const float4*)(src + (size_t)b * NPIX_PER_IMG);
    const int n4 = NPIX_PER_IMG / 4;
    double acc = 0.0;
    int stride = gridDim.x * blockDim.x;
    for (int i = blockIdx.x * blockDim.x + threadIdx.x; i < n4; i += stride) {
        float4 v = img4[i];
        acc += (double)((v.x + v.y) + (v.z + v.w));
    }

    __shared__ double red[256];
    red[threadIdx.x] = acc;
    __syncthreads();
    for (int s = 128; s > 0; s >>= 1) {
        if (threadIdx.x < s) red[threadIdx.x] += red[threadIdx.x + s];
        __syncthreads();
    }
    if (threadIdx.x == 0) atomicAdd(&g_sums2[0][b], red[0]);
}

// ---------------------------------------------------------------------------
__device__ __forceinline__ float clip01(float v) {
    return fminf(fmaxf(v, 0.f), 1.f);
}

// Bilinear sample matching the JAX reference: validity tested on un-clipped
// corner coords, indices clipped, OOB corners read FILL.
__device__ __forceinline__ void bilinear_sample(
    const float* __restrict__ img, float xi, float yi, float* __restrict__ o)
{
    float x0 = floorf(xi), y0 = floorf(yi);
    float wx = xi - x0,    wy = yi - y0;

    float wgt0 = (1.f - wx) * (1.f - wy);
    float wgt1 = wx         * (1.f - wy);
    float wgt2 = (1.f - wx) * wy;
    float wgt3 = wx         * wy;
    float wgt[4] = { wgt0, wgt1, wgt2, wgt3 };

    o[0] = 0.f; o[1] = 0.f; o[2] = 0.f;

#pragma unroll
    for (int k = 0; k < 4; ++k) {
        float xx = x0 + (float)(k & 1);
        float yy = y0 + (float)(k >> 1);
        bool valid = (xx >= 0.f) && (xx <= (float)(W - 1)) &&
                     (yy >= 0.f) && (yy <= (float)(H - 1));
        int xc = (int)fminf(fmaxf(xx, 0.f), (float)(W - 1));
        int yc = (int)fminf(fmaxf(yy, 0.f), (float)(H - 1));
        const float* p = img + ((size_t)yc * W + xc) * C;
        float w = wgt[k];
#pragma unroll
        for (int c = 0; c < C; ++c) {
            float v = valid ? p[c] : FILL_V;
            o[c] += w * v;
        }
    }
}

// ---------------------------------------------------------------------------
// Distort kernel: one thread per QUAD of 4 consecutive x-pixels (12 floats).
// Stores are 3x float4. Enhancement loads are 3x float4. grid=(NQUAD/256, B).
// Branch is uniform per image -> per block: zero divergence.
__global__ __launch_bounds__(256) void distort_kernel(
    const float* __restrict__ src,
    float* __restrict__ dst,
    const int* __restrict__ op_ids,
    const int* __restrict__ signs,
    int layer)
{
    int b   = blockIdx.y;
    int qid = blockIdx.x * blockDim.x + threadIdx.x;   // 0 .. NQUAD-1
    int x4  = (qid & (W / 4 - 1)) << 2;                // 0,4,...,508
    int y   = qid >> 7;                                // qid / 128

    const float* img = src + (size_t)b * NPIX_PER_IMG;
    float* outp      = dst + (size_t)b * NPIX_PER_IMG + (size_t)qid * 12;

    int   op = op_ids[b * NUM_LAYERS + layer];
    float s  = 2.0f * (float)signs[b * NUM_LAYERS + layer] - 1.0f;

    float o[12];

    if (op <= 4) {
        // --- affine: inverse map about center, bilinear resample ---
        float a11, a12, a21, a22, tx, ty;
        if (op == 0) {           // rotate
            float th = s * ROT_RAD;
            float co = cosf(th), si = sinf(th);
            a11 = co;  a12 = si;  a21 = -si; a22 = co;  tx = 0.f; ty = 0.f;
        } else if (op == 1) {    // shear_x
            float sh = s * SHEAR_AMT;
            a11 = 1.f; a12 = -sh; a21 = 0.f; a22 = 1.f; tx = 0.f; ty = 0.f;
        } else if (op == 2) {    // shear_y
            float sh = s * SHEAR_AMT;
            a11 = 1.f; a12 = 0.f; a21 = -sh; a22 = 1.f; tx = 0.f; ty = 0.f;
        } else if (op == 3) {    // trans_x
            a11 = 1.f; a12 = 0.f; a21 = 0.f; a22 = 1.f; tx = -s * TRANS_AMT; ty = 0.f;
        } else {                 // trans_y
            a11 = 1.f; a12 = 0.f; a21 = 0.f; a22 = 1.f; tx = 0.f; ty = -s * TRANS_AMT;
        }
        float dy = (float)y - CENTER;
#pragma unroll
        for (int p = 0; p < 4; ++p) {
            float dx = (float)(x4 + p) - CENTER;
            float xi = a11 * dx + a12 * dy + tx + CENTER;
            float yi = a21 * dx + a22 * dy + ty + CENTER;
            bilinear_sample(img, xi, yi, &o[p * 3]);
        }
    } else if (op == 5 || op == 6) {
        // --- pointwise enhancement: float4 in, float4 out ---
        float f = (s > 0.f) ? ENH_F : INV_ENH_F;
        float m = 0.f;
        if (op == 6)
            m = (float)(g_sums2[layer][b] * (1.0 / (double)NPIX_PER_IMG));
        const float4* in4 = (const float4*)(img + (size_t)qid * 12);
#pragma unroll
        for (int k = 0; k < 3; ++k) {
            float4 v = in4[k];
            o[k*4+0] = clip01(m + f * (v.x - m));
            o[k*4+1] = clip01(m + f * (v.y - m));
            o[k*4+2] = clip01(m + f * (v.z - m));
            o[k*4+3] = clip01(m + f * (v.w - m));
        }
    } else {
        // --- sharpness: 3x3 PIL smooth, edge-clamped; register-tiled quad ---
        float f = (s > 0.f) ? ENH_F : INV_ENH_F;
        const float inv13 = 1.0f / 13.0f;
        float sm[12];
        float cen[12];
#pragma unroll
        for (int k = 0; k < 12; ++k) sm[k] = 0.f;

#pragma unroll
        for (int i = 0; i < 3; ++i) {
            int yy = min(max(y + i - 1, 0), H - 1);
            const float* rp = img + (size_t)yy * W * C;
            float row[18];   // pixels x4-1 .. x4+4 (clamped), 3 channels each
#pragma unroll
            for (int j = 0; j < 6; ++j) {
                int xx = min(max(x4 - 1 + j, 0), W - 1);
                const float* p = rp + (size_t)xx * C;
                row[j*3+0] = p[0];
                row[j*3+1] = p[1];
                row[j*3+2] = p[2];
            }
            if (i == 1) {
#pragma unroll
                for (int p = 0; p < 4; ++p) {
                    cen[p*3+0] = row[(p+1)*3+0];
                    cen[p*3+1] = row[(p+1)*3+1];
                    cen[p*3+2] = row[(p+1)*3+2];
                }
            }
#pragma unroll
            for (int p = 0; p < 4; ++p) {
#pragma unroll
                for (int j = 0; j < 3; ++j) {
                    float kw = ((i == 1 && j == 1) ? 5.0f : 1.0f) * inv13;
#pragma unroll
                    for (int c = 0; c < C; ++c)
                        sm[p*3+c] += kw * row[(p+j)*3+c];
                }
            }
        }
#pragma unroll
        for (int k = 0; k < 12; ++k)
            o[k] = clip01(sm[k] + f * (cen[k] - sm[k]));
    }

    // vectorized store: 3x float4 (48B per thread, fully coalesced)
    float4* o4 = (float4*)outp;
    o4[0] = make_float4(o[0], o[1], o[2],  o[3]);
    o4[1] = make_float4(o[4], o[5], o[6],  o[7]);
    o4[2] = make_float4(o[8], o[9], o[10], o[11]);

    // Layer 0 only: accumulate this image's output sum if layer-1 op is
    // contrast (block-uniform condition -> __syncthreads is safe).
    if (layer == 0 && op_ids[b * NUM_LAYERS + 1] == 6) {
        float local = 0.f;
#pragma unroll
        for (int k = 0; k < 12; ++k) local += o[k];
#pragma unroll
        for (int off = 16; off > 0; off >>= 1)
            local += __shfl_down_sync(0xffffffffu, local, off);
        __shared__ float wsum[8];
        int wid = threadIdx.x >> 5;
        if ((threadIdx.x & 31) == 0) wsum[wid] = local;
        __syncthreads();
        if (threadIdx.x == 0) {
            float tot = 0.f;
#pragma unroll
            for (int w = 0; w < 8; ++w) tot += wsum[w];
            atomicAdd(&g_sums2[1][b], (double)tot);
        }
    }
}

// ---------------------------------------------------------------------------
extern "C" void kernel_launch(void* const* d_in, const int* in_sizes, int n_in,
                              void* d_out, int out_size)
{
    const float* images = (const float*)d_in[0];
    const int*   op_ids = (const int*)d_in[1];
    const int*   signs  = (const int*)d_in[2];
    float* out = (float*)d_out;

    float* scratch;
    cudaGetSymbolAddress((void**)&scratch, g_scratch);
    void* sums_addr;
    cudaGetSymbolAddress(&sums_addr, g_sums2);

    // zero both layers' sum accumulators in one async memset
    cudaMemsetAsync(sums_addr, 0, sizeof(double) * 2 * B);

    dim3 dgrid(NQUAD / 256, B);
    dim3 mgrid(48, B);

    // Layer 0: images -> scratch (also accumulates layer-1 contrast sums)
    mean_kernel<<<mgrid, 256>>>(images, op_ids);
    distort_kernel<<<dgrid, 256>>>(images, scratch, op_ids, signs, 0);

    // Layer 1: scratch -> out
    distort_kernel<<<dgrid, 256>>>(scratch, out, op_ids, signs, 1);
}